// round 2
// baseline (speedup 1.0000x reference)
#include <cuda_runtime.h>

#define NB 2
#define NS 2048
#define ND 1024
#define NH 16
#define NDH 64

// Scratch for projected Q/K/V in [b,h,s,dh] layout. Q is pre-scaled by 1/sqrt(DH).
__device__ float g_Q[NB * NH * NS * NDH];
__device__ float g_K[NB * NH * NS * NDH];
__device__ float g_V[NB * NH * NS * NDH];

// ---------------------------------------------------------------------------
// Projection GEMM: dst[b,h,s,dh] = scale * sum_k x[b,s,k] * W[k, h*DH+dh]
// M = NB*NS = 4096, N = ND = 1024, K = ND = 1024.
// 64x64 block tile, K-tile 16, 256 threads, 4x4 micro-tile per thread.
// ---------------------------------------------------------------------------
__global__ __launch_bounds__(256) void proj_kernel(const float* __restrict__ x,
                                                   const float* __restrict__ W,
                                                   float scale, int which)
{
    float* dst = (which == 0) ? g_Q : (which == 1) ? g_K : g_V;

    __shared__ float As[64][16];
    __shared__ float Bs[16][64];

    const int tx = threadIdx.x;
    const int ty = threadIdx.y;
    const int tid = ty * 16 + tx;
    const int m0 = blockIdx.y * 64;
    const int n0 = blockIdx.x * 64;

    // Per-thread load coordinates (float4 loads)
    const int ar = (tid * 4) >> 4;   // 0..63
    const int ac = (tid * 4) & 15;   // 0,4,8,12
    const int br = (tid * 4) >> 6;   // 0..15
    const int bc = (tid * 4) & 63;   // 0..60 step 4

    float acc[4][4];
    #pragma unroll
    for (int i = 0; i < 4; i++)
        #pragma unroll
        for (int j = 0; j < 4; j++)
            acc[i][j] = 0.0f;

    for (int k0 = 0; k0 < ND; k0 += 16) {
        float4 av = *(const float4*)(x + (size_t)(m0 + ar) * ND + k0 + ac);
        float4 bv = *(const float4*)(W + (size_t)(k0 + br) * ND + n0 + bc);
        *(float4*)&As[ar][ac] = av;
        *(float4*)&Bs[br][bc] = bv;
        __syncthreads();

        #pragma unroll
        for (int kk = 0; kk < 16; kk++) {
            float4 b = *(float4*)&Bs[kk][tx * 4];
            #pragma unroll
            for (int i = 0; i < 4; i++) {
                float a = As[ty * 4 + i][kk];
                acc[i][0] += a * b.x;
                acc[i][1] += a * b.y;
                acc[i][2] += a * b.z;
                acc[i][3] += a * b.w;
            }
        }
        __syncthreads();
    }

    // Epilogue: scatter into [b,h,s,dh] layout (tile never crosses b or h).
    const int b = m0 / NS;
    const int h = n0 / NDH;
    #pragma unroll
    for (int i = 0; i < 4; i++) {
        int s = m0 + ty * 4 + i - b * NS;
        float4 o;
        o.x = acc[i][0] * scale;
        o.y = acc[i][1] * scale;
        o.z = acc[i][2] * scale;
        o.w = acc[i][3] * scale;
        *(float4*)(dst + ((size_t)(b * NH + h) * NS + s) * NDH + tx * 4) = o;
    }
}

// ---------------------------------------------------------------------------
// Flash attention (causal), fp32, online softmax.
// One block = one (b,h) x one 64-query tile. 256 threads (16x16),
// each thread owns a 4x4 patch of the 64x64 score tile and of the 64x64
// output tile. Row-wise softmax stats reduced with shfl over the 16 tx lanes.
// Q is pre-scaled by 1/sqrt(DH) in the projection.
// ---------------------------------------------------------------------------
#define SM_QS   (64 * 65)          // Qs[r][d], stride 65 (bank-conflict pad)
#define SM_TILE (64 * 68)          // Kt/Vs/Ps, stride 68 (float4-aligned pad)
#define SMEM_FLOATS (SM_QS + 3 * SM_TILE)
#define SMEM_BYTES  (SMEM_FLOATS * 4)

__global__ __launch_bounds__(256) void attn_kernel(float* __restrict__ out)
{
    extern __shared__ float sm[];
    float* Qs = sm;                      // [64][65]   q-rows major
    float* Kt = sm + SM_QS;              // [64][68]   [d][c]  (transposed K tile)
    float* Vs = Kt + SM_TILE;            // [64][68]   [k][d]
    float* Ps = Vs + SM_TILE;            // [64][68]   [r][c]  probabilities

    const int tx = threadIdx.x;
    const int ty = threadIdx.y;
    const int tid = ty * 16 + tx;
    const int bh = blockIdx.y;
    const int qt = gridDim.x - 1 - blockIdx.x;   // big q-tiles launch first
    const int q0 = qt * 64;

    const float* __restrict__ Qg = g_Q + (size_t)bh * NS * NDH;
    const float* __restrict__ Kg = g_K + (size_t)bh * NS * NDH;
    const float* __restrict__ Vg = g_V + (size_t)bh * NS * NDH;

    // Load Q tile (64x64) once.
    #pragma unroll
    for (int t = 0; t < 16; t++) {
        int idx = tid + t * 256;
        int r = idx >> 6, d = idx & 63;
        Qs[r * 65 + d] = Qg[(size_t)(q0 + r) * NDH + d];
    }

    float m[4], l[4], o[4][4];
    #pragma unroll
    for (int i = 0; i < 4; i++) {
        m[i] = -1e30f;
        l[i] = 0.0f;
        #pragma unroll
        for (int j = 0; j < 4; j++) o[i][j] = 0.0f;
    }

    for (int kt = 0; kt <= qt; kt++) {
        const int k0 = kt * 64;

        __syncthreads();   // protect Kt/Vs/Ps from previous iteration's readers
        #pragma unroll
        for (int t = 0; t < 16; t++) {
            int idx = tid + t * 256;
            int c = idx >> 6, d = idx & 63;
            float kv = Kg[(size_t)(k0 + c) * NDH + d];
            float vv = Vg[(size_t)(k0 + c) * NDH + d];
            Kt[d * 68 + c] = kv;       // transposed store
            Vs[c * 68 + d] = vv;
        }
        __syncthreads();

        // S = Q K^T   (each thread: rows ty*4.., cols tx*4..)
        float s[4][4];
        #pragma unroll
        for (int i = 0; i < 4; i++)
            #pragma unroll
            for (int j = 0; j < 4; j++)
                s[i][j] = 0.0f;

        #pragma unroll 4
        for (int d = 0; d < 64; d++) {
            float4 kv = *(float4*)&Kt[d * 68 + tx * 4];
            #pragma unroll
            for (int i = 0; i < 4; i++) {
                float qv = Qs[(ty * 4 + i) * 65 + d];
                s[i][0] += qv * kv.x;
                s[i][1] += qv * kv.y;
                s[i][2] += qv * kv.z;
                s[i][3] += qv * kv.w;
            }
        }

        // Causal mask on the diagonal tile.
        if (kt == qt) {
            #pragma unroll
            for (int i = 0; i < 4; i++)
                #pragma unroll
                for (int j = 0; j < 4; j++)
                    if (k0 + tx * 4 + j > q0 + ty * 4 + i) s[i][j] = -1e30f;
        }

        // Online softmax per row; row stats reduced across the 16 tx lanes.
        #pragma unroll
        for (int i = 0; i < 4; i++) {
            float mx = fmaxf(fmaxf(s[i][0], s[i][1]), fmaxf(s[i][2], s[i][3]));
            #pragma unroll
            for (int off = 1; off < 16; off <<= 1)
                mx = fmaxf(mx, __shfl_xor_sync(0xffffffffu, mx, off));

            float mnew  = fmaxf(m[i], mx);
            float alpha = __expf(m[i] - mnew);

            float ps = 0.0f;
            #pragma unroll
            for (int j = 0; j < 4; j++) {
                s[i][j] = __expf(s[i][j] - mnew);
                ps += s[i][j];
            }
            #pragma unroll
            for (int off = 1; off < 16; off <<= 1)
                ps += __shfl_xor_sync(0xffffffffu, ps, off);

            l[i] = l[i] * alpha + ps;
            m[i] = mnew;
            #pragma unroll
            for (int j = 0; j < 4; j++) o[i][j] *= alpha;

            *(float4*)&Ps[(ty * 4 + i) * 68 + tx * 4] =
                make_float4(s[i][0], s[i][1], s[i][2], s[i][3]);
        }
        __syncthreads();

        // O += P V   (each thread: rows ty*4.., dh cols tx*4..)
        #pragma unroll 4
        for (int k = 0; k < 64; k++) {
            float4 v = *(float4*)&Vs[k * 68 + tx * 4];
            #pragma unroll
            for (int i = 0; i < 4; i++) {
                float p = Ps[(ty * 4 + i) * 68 + k];
                o[i][0] += p * v.x;
                o[i][1] += p * v.y;
                o[i][2] += p * v.z;
                o[i][3] += p * v.w;
            }
        }
    }

    // Normalize and write out[b, s, h*DH + dh].
    const int b = bh / NH;
    const int h = bh % NH;
    #pragma unroll
    for (int i = 0; i < 4; i++) {
        int q = q0 + ty * 4 + i;
        float inv = 1.0f / l[i];
        float4 ov = make_float4(o[i][0] * inv, o[i][1] * inv,
                                o[i][2] * inv, o[i][3] * inv);
        *(float4*)(out + ((size_t)(b * NS + q) * ND) + h * NDH + tx * 4) = ov;
    }
}

// ---------------------------------------------------------------------------
extern "C" void kernel_launch(void* const* d_in, const int* in_sizes, int n_in,
                              void* d_out, int out_size)
{
    const float* x  = (const float*)d_in[0];
    const float* Wq = (const float*)d_in[1];
    const float* Wk = (const float*)d_in[2];
    const float* Wv = (const float*)d_in[3];
    float* out = (float*)d_out;

    dim3 blk(16, 16);

    dim3 gproj(ND / 64, (NB * NS) / 64);
    proj_kernel<<<gproj, blk>>>(x, Wq, 0.125f, 0);   // 1/sqrt(64) folded into Q
    proj_kernel<<<gproj, blk>>>(x, Wk, 1.0f, 1);
    proj_kernel<<<gproj, blk>>>(x, Wv, 1.0f, 2);

    cudaFuncSetAttribute(attn_kernel, cudaFuncAttributeMaxDynamicSharedMemorySize,
                         SMEM_BYTES);

    dim3 gattn(NS / 64, NB * NH);
    attn_kernel<<<gattn, blk, SMEM_BYTES>>>(out);
}

// round 4
// speedup vs baseline: 1.2926x; 1.2926x over previous
#include <cuda_runtime.h>
#include <mma.h>

using namespace nvcuda;

#define NB 2
#define NS 2048
#define ND 1024
#define NH 16
#define NDH 64

// Scratch for projected Q/K/V in [b,h,s,dh] layout. Q pre-scaled by 1/sqrt(DH).
__device__ float g_Q[NB * NH * NS * NDH];
__device__ float g_K[NB * NH * NS * NDH];
__device__ float g_V[NB * NH * NS * NDH];

// ---------------------------------------------------------------------------
// Projection GEMM on tensor cores (tf32 wmma m16n16k8).
// dst[b,h,s,dh] = scale * sum_k x[b,s,k] * W[k, h*DH+dh]
// M = NB*NS = 4096, N = ND = 1024, K = ND = 1024.
// Block: 256 threads (8 warps as 4x2), tile 128(M) x 64(N), K-tile 16.
// Each warp: 32x32 = 2x2 wmma 16x16 fragments. blockIdx.z selects W.
// ---------------------------------------------------------------------------
#define AS_STRIDE 20   // 16 + pad, multiple of 4 (tf32 ldm requirement)
#define BS_STRIDE 68   // 64 + pad, multiple of 4

__global__ __launch_bounds__(256) void proj_tc_kernel(const float* __restrict__ x,
                                                      const float* __restrict__ Wq,
                                                      const float* __restrict__ Wk,
                                                      const float* __restrict__ Wv)
{
    __shared__ float As[128 * AS_STRIDE];  // x tile  [m][k]
    __shared__ float Bs[16 * BS_STRIDE];   // W tile  [k][n]

    const int which = blockIdx.z;
    const float* __restrict__ W = (which == 0) ? Wq : (which == 1) ? Wk : Wv;
    float* dst = (which == 0) ? g_Q : (which == 1) ? g_K : g_V;
    const float scale = (which == 0) ? 0.125f : 1.0f;  // 1/sqrt(64) folded into Q

    const int m0 = blockIdx.y * 128;
    const int n0 = blockIdx.x * 64;
    const int tid = threadIdx.x;
    const int warp = tid >> 5;
    const int wm = warp >> 1;   // 0..3 -> m offset wm*32
    const int wn = warp & 1;    // 0..1 -> n offset wn*32

    // Per-thread load coords
    const int ar = tid >> 1;          // 0..127
    const int ac = (tid & 1) * 8;     // 0 or 8
    const int br = tid >> 4;          // 0..15
    const int bc = (tid & 15) * 4;    // 0..60

    wmma::fragment<wmma::accumulator, 16, 16, 8, float> acc[2][2];
    #pragma unroll
    for (int i = 0; i < 2; i++)
        #pragma unroll
        for (int j = 0; j < 2; j++)
            wmma::fill_fragment(acc[i][j], 0.0f);

    for (int k0 = 0; k0 < ND; k0 += 16) {
        // Load x tile 128x16
        const float* xp = x + (size_t)(m0 + ar) * ND + k0 + ac;
        float4 a0 = *(const float4*)xp;
        float4 a1 = *(const float4*)(xp + 4);
        *(float4*)&As[ar * AS_STRIDE + ac]     = a0;
        *(float4*)&As[ar * AS_STRIDE + ac + 4] = a1;
        // Load W tile 16x64
        float4 bv = *(const float4*)(W + (size_t)(k0 + br) * ND + n0 + bc);
        *(float4*)&Bs[br * BS_STRIDE + bc] = bv;
        __syncthreads();

        #pragma unroll
        for (int ks = 0; ks < 16; ks += 8) {
            wmma::fragment<wmma::matrix_a, 16, 16, 8, wmma::precision::tf32, wmma::row_major> af[2];
            wmma::fragment<wmma::matrix_b, 16, 16, 8, wmma::precision::tf32, wmma::row_major> bf[2];
            #pragma unroll
            for (int i = 0; i < 2; i++) {
                wmma::load_matrix_sync(af[i], &As[(wm * 32 + i * 16) * AS_STRIDE + ks], AS_STRIDE);
                #pragma unroll
                for (int t = 0; t < af[i].num_elements; t++)
                    af[i].x[t] = wmma::__float_to_tf32(af[i].x[t]);
            }
            #pragma unroll
            for (int j = 0; j < 2; j++) {
                wmma::load_matrix_sync(bf[j], &Bs[ks * BS_STRIDE + wn * 32 + j * 16], BS_STRIDE);
                #pragma unroll
                for (int t = 0; t < bf[j].num_elements; t++)
                    bf[j].x[t] = wmma::__float_to_tf32(bf[j].x[t]);
            }
            #pragma unroll
            for (int i = 0; i < 2; i++)
                #pragma unroll
                for (int j = 0; j < 2; j++)
                    wmma::mma_sync(acc[i][j], af[i], bf[j], acc[i][j]);
        }
        __syncthreads();
    }

    // Epilogue: tile lies inside one (b, h). Write [b,h,s,dh], row stride NDH=64.
    const int b = m0 / NS;
    const int h = n0 / NDH;
    float* base = dst + ((size_t)(b * NH + h) * NS + (m0 & (NS - 1))) * NDH;
    #pragma unroll
    for (int i = 0; i < 2; i++)
        #pragma unroll
        for (int j = 0; j < 2; j++) {
            #pragma unroll
            for (int t = 0; t < acc[i][j].num_elements; t++)
                acc[i][j].x[t] *= scale;
            wmma::store_matrix_sync(base + (size_t)(wm * 32 + i * 16) * NDH + wn * 32 + j * 16,
                                    acc[i][j], NDH, wmma::mem_row_major);
        }
}

// ---------------------------------------------------------------------------
// Flash attention (causal), fp32, online softmax. 8x4 micro-tile.
// One block = one (b,h) x one 64-query tile. 128 threads (16x8):
// thread (tx,ty) owns q-rows ty*8..+7, k-cols tx*4..+3.
// Q pre-scaled by 1/sqrt(DH).
// Per d-step: 2 float4 (Q) + 1 float4 (K) per 32 FFMA -> 1.5 B/FFMA.
// ---------------------------------------------------------------------------
#define TS 68                       // tile row stride (64 + 4 pad)
#define SM_T (64 * TS)
#define ATT_SMEM_FLOATS (4 * SM_T)  // Qt, Kt, Vs, Ps
#define ATT_SMEM_BYTES (ATT_SMEM_FLOATS * 4)

__global__ __launch_bounds__(128) void attn_kernel(float* __restrict__ out)
{
    extern __shared__ float sm[];
    float* Qt = sm;                 // [d][q]  transposed Q
    float* Kt = sm + SM_T;          // [d][c]  transposed K
    float* Vs = sm + 2 * SM_T;      // [c][d]
    float* Ps = sm + 3 * SM_T;      // [r][c]  probabilities (row-major)

    const int tx = threadIdx.x;     // 0..15
    const int ty = threadIdx.y;     // 0..7
    const int tid = ty * 16 + tx;
    const int r0 = ty * 8;
    const int c0 = tx * 4;
    const int bh = blockIdx.y;
    const int qt = gridDim.x - 1 - blockIdx.x;   // big q-tiles launch first
    const int q0 = qt * 64;

    const float* __restrict__ Qg = g_Q + (size_t)bh * NS * NDH;
    const float* __restrict__ Kg = g_K + (size_t)bh * NS * NDH;
    const float* __restrict__ Vg = g_V + (size_t)bh * NS * NDH;

    // Load Q tile (64x64) once, transposed into Qt[d][q].
    #pragma unroll
    for (int t = 0; t < 32; t++) {
        int idx = tid + t * 128;
        int r = idx >> 6, d = idx & 63;
        Qt[d * TS + r] = Qg[(size_t)(q0 + r) * NDH + d];
    }

    float m[8], l[8], o[8][4];
    #pragma unroll
    for (int i = 0; i < 8; i++) {
        m[i] = -1e30f;
        l[i] = 0.0f;
        #pragma unroll
        for (int j = 0; j < 4; j++) o[i][j] = 0.0f;
    }

    for (int kt = 0; kt <= qt; kt++) {
        const int k0 = kt * 64;

        __syncthreads();   // protect Kt/Vs/Ps from previous iteration's readers
        #pragma unroll
        for (int t = 0; t < 32; t++) {
            int idx = tid + t * 128;
            int c = idx >> 6, d = idx & 63;
            Kt[d * TS + c] = Kg[(size_t)(k0 + c) * NDH + d];
            Vs[c * TS + d] = Vg[(size_t)(k0 + c) * NDH + d];
        }
        __syncthreads();

        // S = Q K^T : thread computes rows r0..r0+7, cols c0..c0+3.
        float s[8][4];
        #pragma unroll
        for (int i = 0; i < 8; i++)
            #pragma unroll
            for (int j = 0; j < 4; j++)
                s[i][j] = 0.0f;

        #pragma unroll 4
        for (int d = 0; d < 64; d++) {
            float4 kv = *(float4*)&Kt[d * TS + c0];
            float4 qa = *(float4*)&Qt[d * TS + r0];
            float4 qb = *(float4*)&Qt[d * TS + r0 + 4];
            float qr[8] = {qa.x, qa.y, qa.z, qa.w, qb.x, qb.y, qb.z, qb.w};
            #pragma unroll
            for (int i = 0; i < 8; i++) {
                s[i][0] += qr[i] * kv.x;
                s[i][1] += qr[i] * kv.y;
                s[i][2] += qr[i] * kv.z;
                s[i][3] += qr[i] * kv.w;
            }
        }

        // Causal mask on the diagonal tile.
        if (kt == qt) {
            #pragma unroll
            for (int i = 0; i < 8; i++)
                #pragma unroll
                for (int j = 0; j < 4; j++)
                    if (c0 + j > r0 + i) s[i][j] = -1e30f;
        }

        // Online softmax; row stats reduced across the 16 tx lanes
        // (lane = (ty&1)*16 + tx, xor masks 1,2,4,8 stay within each half-warp).
        #pragma unroll
        for (int i = 0; i < 8; i++) {
            float mx = fmaxf(fmaxf(s[i][0], s[i][1]), fmaxf(s[i][2], s[i][3]));
            #pragma unroll
            for (int off = 1; off < 16; off <<= 1)
                mx = fmaxf(mx, __shfl_xor_sync(0xffffffffu, mx, off));

            float mnew  = fmaxf(m[i], mx);
            float alpha = __expf(m[i] - mnew);

            float ps = 0.0f;
            #pragma unroll
            for (int j = 0; j < 4; j++) {
                s[i][j] = __expf(s[i][j] - mnew);
                ps += s[i][j];
            }
            #pragma unroll
            for (int off = 1; off < 16; off <<= 1)
                ps += __shfl_xor_sync(0xffffffffu, ps, off);

            l[i] = l[i] * alpha + ps;
            m[i] = mnew;
            #pragma unroll
            for (int j = 0; j < 4; j++) o[i][j] *= alpha;

            *(float4*)&Ps[(r0 + i) * TS + c0] =
                make_float4(s[i][0], s[i][1], s[i][2], s[i][3]);
        }
        __syncthreads();

        // O += P V : rows r0..r0+7, dh cols c0..c0+3 (reuse tx lanes for dh).
        #pragma unroll 4
        for (int k = 0; k < 64; k++) {
            float4 v = *(float4*)&Vs[k * TS + c0];
            #pragma unroll
            for (int i = 0; i < 8; i++) {
                float p = Ps[(r0 + i) * TS + k];
                o[i][0] += p * v.x;
                o[i][1] += p * v.y;
                o[i][2] += p * v.z;
                o[i][3] += p * v.w;
            }
        }
    }

    // Normalize and write out[b, s, h*DH + dh].
    const int b = bh / NH;
    const int h = bh % NH;
    #pragma unroll
    for (int i = 0; i < 8; i++) {
        int q = q0 + r0 + i;
        float inv = 1.0f / l[i];
        float4 ov = make_float4(o[i][0] * inv, o[i][1] * inv,
                                o[i][2] * inv, o[i][3] * inv);
        *(float4*)(out + ((size_t)(b * NS + q) * ND) + h * NDH + c0) = ov;
    }
}

// ---------------------------------------------------------------------------
extern "C" void kernel_launch(void* const* d_in, const int* in_sizes, int n_in,
                              void* d_out, int out_size)
{
    const float* x  = (const float*)d_in[0];
    const float* Wq = (const float*)d_in[1];
    const float* Wk = (const float*)d_in[2];
    const float* Wv = (const float*)d_in[3];
    float* out = (float*)d_out;

    dim3 gproj(ND / 64, (NB * NS) / 128, 3);
    proj_tc_kernel<<<gproj, 256>>>(x, Wq, Wk, Wv);

    cudaFuncSetAttribute(attn_kernel, cudaFuncAttributeMaxDynamicSharedMemorySize,
                         ATT_SMEM_BYTES);
    dim3 gattn(NS / 64, NB * NH);
    attn_kernel<<<gattn, dim3(16, 8), ATT_SMEM_BYTES>>>(out);
}

// round 5
// speedup vs baseline: 1.3757x; 1.0643x over previous
#include <cuda_runtime.h>
#include <mma.h>

using namespace nvcuda;

#define NB 2
#define NS 2048
#define ND 1024
#define NH 16
#define NDH 64
#define XN (NB * NS * ND)      // 4194304
#define WN (ND * ND)           // 1048576 = 2^20

// Scratch: projected Q/K/V in [b,h,s,dh] layout (Q pre-scaled by 1/sqrt(DH)),
// plus tf32-pre-rounded copies of x and the three weight matrices.
__device__ float g_Q[NB * NH * NS * NDH];
__device__ float g_K[NB * NH * NS * NDH];
__device__ float g_V[NB * NH * NS * NDH];
__device__ float g_xc[XN];
__device__ float g_Wc[3 * WN];

// ---------------------------------------------------------------------------
// cvt_kernel: round x / Wq / Wk / Wv to tf32 (RNA) once. Wq gets 0.125 folded.
// Exactly (XN + 3*WN)/4 float4s = 1835008 = 7168 blocks * 256 threads.
// ---------------------------------------------------------------------------
__global__ __launch_bounds__(256) void cvt_kernel(const float* __restrict__ x,
                                                  const float* __restrict__ Wq,
                                                  const float* __restrict__ Wk,
                                                  const float* __restrict__ Wv)
{
    size_t e = ((size_t)blockIdx.x * 256 + threadIdx.x) * 4;
    const float* src;
    float* dst;
    float sc = 1.0f;
    if (e < XN) {
        src = x + e;
        dst = g_xc + e;
    } else {
        size_t r = e - XN;
        int w = (int)(r >> 20);
        size_t off = r & (WN - 1);
        src = (w == 0 ? Wq : (w == 1 ? Wk : Wv)) + off;
        dst = g_Wc + (size_t)w * WN + off;
        if (w == 0) sc = 0.125f;   // 1/sqrt(64) folded into Wq
    }
    float4 v = *(const float4*)src;
    v.x = wmma::__float_to_tf32(v.x * sc);
    v.y = wmma::__float_to_tf32(v.y * sc);
    v.z = wmma::__float_to_tf32(v.z * sc);
    v.w = wmma::__float_to_tf32(v.w * sc);
    *(float4*)dst = v;
}

// ---------------------------------------------------------------------------
// Projection GEMM v2: 128x128 tile, K-tile 32, 3-stage cp.async pipeline.
// dst[b,h,s,dh] = sum_k xc[b,s,k] * Wc[k, h*DH+dh]   (inputs pre-tf32)
// 256 threads = 8 warps (2 m x 4 n), warp tile 64x32 = 4x2 wmma m16n16k8.
// One __syncthreads per k-iter. blockIdx.z selects the weight matrix.
// ---------------------------------------------------------------------------
#define PKT 32                 // K-tile
#define AS_S 40                // As row stride (32 + 8): 160B -> bank rotation
#define BS_S 132               // Bs row stride (128 + 4): 528B -> bank rotation
#define STG 3
#define STAGE_FLOATS (128 * AS_S + PKT * BS_S)     // 5120 + 4224 = 9344
#define PROJ_SMEM_BYTES (STG * STAGE_FLOATS * 4)   // 112128 B

__device__ __forceinline__ void cpa16(float* dst, const float* src) {
    unsigned sd = (unsigned)__cvta_generic_to_shared(dst);
    asm volatile("cp.async.cg.shared.global [%0], [%1], 16;\n" :: "r"(sd), "l"(src));
}

__global__ __launch_bounds__(256, 2) void proj_tc2()
{
    extern __shared__ float sh[];

    const int which = blockIdx.z;
    const float* __restrict__ W = g_Wc + (size_t)which * WN;
    float* dst = (which == 0) ? g_Q : (which == 1) ? g_K : g_V;

    const int m0 = blockIdx.y * 128;
    const int n0 = blockIdx.x * 128;
    const int tid = threadIdx.x;
    const int warp = tid >> 5;
    const int wm = warp >> 2;          // 0..1 -> m offset wm*64
    const int wn = warp & 3;           // 0..3 -> n offset wn*32

    // cp.async coordinates (4 x 16B for A, 4 x 16B for B per thread per iter)
    const float* __restrict__ xbase = g_xc + (size_t)m0 * ND;

    wmma::fragment<wmma::accumulator, 16, 16, 8, float> acc[4][2];
    #pragma unroll
    for (int i = 0; i < 4; i++)
        #pragma unroll
        for (int j = 0; j < 2; j++)
            wmma::fill_fragment(acc[i][j], 0.0f);

    // Issue one stage's loads (A: 128x32, B: 32x128) for k-iter ki into stage st.
    auto issue = [&](int ki, int st) {
        float* As = sh + st * STAGE_FLOATS;
        float* Bs = As + 128 * AS_S;
        const int kk0 = ki * PKT;
        #pragma unroll
        for (int i = 0; i < 4; i++) {
            int f = tid + i * 256;
            int row = f >> 3, c = (f & 7) * 4;
            cpa16(&As[row * AS_S + c], xbase + (size_t)row * ND + kk0 + c);
        }
        #pragma unroll
        for (int i = 0; i < 4; i++) {
            int f = tid + i * 256;
            int k = f >> 5, n = (f & 31) * 4;
            cpa16(&Bs[k * BS_S + n], W + (size_t)(kk0 + k) * ND + n0 + n);
        }
        asm volatile("cp.async.commit_group;\n");
    };

    issue(0, 0);
    issue(1, 1);

    const int NIT = ND / PKT;   // 32
    for (int it = 0; it < NIT; it++) {
        if (it < NIT - 2) {
            asm volatile("cp.async.wait_group 1;\n");
        } else {
            asm volatile("cp.async.wait_group 0;\n");
        }
        __syncthreads();
        if (it + 2 < NIT) issue(it + 2, (it + 2) % 3);

        const float* As = sh + (it % 3) * STAGE_FLOATS;
        const float* Bs = As + 128 * AS_S;

        #pragma unroll
        for (int ks = 0; ks < 4; ks++) {
            wmma::fragment<wmma::matrix_a, 16, 16, 8, wmma::precision::tf32, wmma::row_major> af[4];
            wmma::fragment<wmma::matrix_b, 16, 16, 8, wmma::precision::tf32, wmma::row_major> bf[2];
            #pragma unroll
            for (int i = 0; i < 4; i++)
                wmma::load_matrix_sync(af[i], &As[(wm * 64 + i * 16) * AS_S + ks * 8], AS_S);
            #pragma unroll
            for (int j = 0; j < 2; j++)
                wmma::load_matrix_sync(bf[j], &Bs[(ks * 8) * BS_S + wn * 32 + j * 16], BS_S);
            #pragma unroll
            for (int i = 0; i < 4; i++)
                #pragma unroll
                for (int j = 0; j < 2; j++)
                    wmma::mma_sync(acc[i][j], af[i], bf[j], acc[i][j]);
        }
    }

    // Epilogue: scatter into [b,h,s,dh]. Each 16x16 frag stays in one (b,h).
    #pragma unroll
    for (int i = 0; i < 4; i++) {
        int gm = m0 + wm * 64 + i * 16;
        int b = gm >> 11;            // /NS
        int s = gm & (NS - 1);
        #pragma unroll
        for (int j = 0; j < 2; j++) {
            int gn = n0 + wn * 32 + j * 16;
            int h = gn >> 6;
            int col = gn & 63;
            float* base = dst + ((size_t)(b * NH + h) * NS + s) * NDH + col;
            wmma::store_matrix_sync(base, acc[i][j], NDH, wmma::mem_row_major);
        }
    }
}

// ---------------------------------------------------------------------------
// Flash attention (causal), fp32, online softmax. 8x4 micro-tile.
// UNCHANGED from round 4 (measured 552.7us, ~88% of fp32 FFMA ceiling).
// ---------------------------------------------------------------------------
#define TS 68                       // tile row stride (64 + 4 pad)
#define SM_T (64 * TS)
#define ATT_SMEM_FLOATS (4 * SM_T)  // Qt, Kt, Vs, Ps
#define ATT_SMEM_BYTES (ATT_SMEM_FLOATS * 4)

__global__ __launch_bounds__(128) void attn_kernel(float* __restrict__ out)
{
    extern __shared__ float sm[];
    float* Qt = sm;                 // [d][q]  transposed Q
    float* Kt = sm + SM_T;          // [d][c]  transposed K
    float* Vs = sm + 2 * SM_T;      // [c][d]
    float* Ps = sm + 3 * SM_T;      // [r][c]  probabilities (row-major)

    const int tx = threadIdx.x;     // 0..15
    const int ty = threadIdx.y;     // 0..7
    const int tid = ty * 16 + tx;
    const int r0 = ty * 8;
    const int c0 = tx * 4;
    const int bh = blockIdx.y;
    const int qt = gridDim.x - 1 - blockIdx.x;   // big q-tiles launch first
    const int q0 = qt * 64;

    const float* __restrict__ Qg = g_Q + (size_t)bh * NS * NDH;
    const float* __restrict__ Kg = g_K + (size_t)bh * NS * NDH;
    const float* __restrict__ Vg = g_V + (size_t)bh * NS * NDH;

    // Load Q tile (64x64) once, transposed into Qt[d][q].
    #pragma unroll
    for (int t = 0; t < 32; t++) {
        int idx = tid + t * 128;
        int r = idx >> 6, d = idx & 63;
        Qt[d * TS + r] = Qg[(size_t)(q0 + r) * NDH + d];
    }

    float m[8], l[8], o[8][4];
    #pragma unroll
    for (int i = 0; i < 8; i++) {
        m[i] = -1e30f;
        l[i] = 0.0f;
        #pragma unroll
        for (int j = 0; j < 4; j++) o[i][j] = 0.0f;
    }

    for (int kt = 0; kt <= qt; kt++) {
        const int k0 = kt * 64;

        __syncthreads();   // protect Kt/Vs/Ps from previous iteration's readers
        #pragma unroll
        for (int t = 0; t < 32; t++) {
            int idx = tid + t * 128;
            int c = idx >> 6, d = idx & 63;
            Kt[d * TS + c] = Kg[(size_t)(k0 + c) * NDH + d];
            Vs[c * TS + d] = Vg[(size_t)(k0 + c) * NDH + d];
        }
        __syncthreads();

        // S = Q K^T : thread computes rows r0..r0+7, cols c0..c0+3.
        float s[8][4];
        #pragma unroll
        for (int i = 0; i < 8; i++)
            #pragma unroll
            for (int j = 0; j < 4; j++)
                s[i][j] = 0.0f;

        #pragma unroll 4
        for (int d = 0; d < 64; d++) {
            float4 kv = *(float4*)&Kt[d * TS + c0];
            float4 qa = *(float4*)&Qt[d * TS + r0];
            float4 qb = *(float4*)&Qt[d * TS + r0 + 4];
            float qr[8] = {qa.x, qa.y, qa.z, qa.w, qb.x, qb.y, qb.z, qb.w};
            #pragma unroll
            for (int i = 0; i < 8; i++) {
                s[i][0] += qr[i] * kv.x;
                s[i][1] += qr[i] * kv.y;
                s[i][2] += qr[i] * kv.z;
                s[i][3] += qr[i] * kv.w;
            }
        }

        // Causal mask on the diagonal tile.
        if (kt == qt) {
            #pragma unroll
            for (int i = 0; i < 8; i++)
                #pragma unroll
                for (int j = 0; j < 4; j++)
                    if (c0 + j > r0 + i) s[i][j] = -1e30f;
        }

        // Online softmax; row stats reduced across the 16 tx lanes
        // (lane = (ty&1)*16 + tx, xor masks 1,2,4,8 stay within each half-warp).
        #pragma unroll
        for (int i = 0; i < 8; i++) {
            float mx = fmaxf(fmaxf(s[i][0], s[i][1]), fmaxf(s[i][2], s[i][3]));
            #pragma unroll
            for (int off = 1; off < 16; off <<= 1)
                mx = fmaxf(mx, __shfl_xor_sync(0xffffffffu, mx, off));

            float mnew  = fmaxf(m[i], mx);
            float alpha = __expf(m[i] - mnew);

            float ps = 0.0f;
            #pragma unroll
            for (int j = 0; j < 4; j++) {
                s[i][j] = __expf(s[i][j] - mnew);
                ps += s[i][j];
            }
            #pragma unroll
            for (int off = 1; off < 16; off <<= 1)
                ps += __shfl_xor_sync(0xffffffffu, ps, off);

            l[i] = l[i] * alpha + ps;
            m[i] = mnew;
            #pragma unroll
            for (int j = 0; j < 4; j++) o[i][j] *= alpha;

            *(float4*)&Ps[(r0 + i) * TS + c0] =
                make_float4(s[i][0], s[i][1], s[i][2], s[i][3]);
        }
        __syncthreads();

        // O += P V : rows r0..r0+7, dh cols c0..c0+3 (reuse tx lanes for dh).
        #pragma unroll 4
        for (int k = 0; k < 64; k++) {
            float4 v = *(float4*)&Vs[k * TS + c0];
            #pragma unroll
            for (int i = 0; i < 8; i++) {
                float p = Ps[(r0 + i) * TS + k];
                o[i][0] += p * v.x;
                o[i][1] += p * v.y;
                o[i][2] += p * v.z;
                o[i][3] += p * v.w;
            }
        }
    }

    // Normalize and write out[b, s, h*DH + dh].
    const int b = bh / NH;
    const int h = bh % NH;
    #pragma unroll
    for (int i = 0; i < 8; i++) {
        int q = q0 + r0 + i;
        float inv = 1.0f / l[i];
        float4 ov = make_float4(o[i][0] * inv, o[i][1] * inv,
                                o[i][2] * inv, o[i][3] * inv);
        *(float4*)(out + ((size_t)(b * NS + q) * ND) + h * NDH + c0) = ov;
    }
}

// ---------------------------------------------------------------------------
extern "C" void kernel_launch(void* const* d_in, const int* in_sizes, int n_in,
                              void* d_out, int out_size)
{
    const float* x  = (const float*)d_in[0];
    const float* Wq = (const float*)d_in[1];
    const float* Wk = (const float*)d_in[2];
    const float* Wv = (const float*)d_in[3];
    float* out = (float*)d_out;

    // 1. tf32 pre-round (Wq scaled by 1/sqrt(DH))
    cvt_kernel<<<(XN + 3 * WN) / 4 / 256, 256>>>(x, Wq, Wk, Wv);

    // 2. Q/K/V projections on tensor cores
    cudaFuncSetAttribute(proj_tc2, cudaFuncAttributeMaxDynamicSharedMemorySize,
                         PROJ_SMEM_BYTES);
    dim3 gproj(ND / 128, (NB * NS) / 128, 3);
    proj_tc2<<<gproj, 256, PROJ_SMEM_BYTES>>>();

    // 3. causal flash attention
    cudaFuncSetAttribute(attn_kernel, cudaFuncAttributeMaxDynamicSharedMemorySize,
                         ATT_SMEM_BYTES);
    dim3 gattn(NS / 64, NB * NH);
    attn_kernel<<<gattn, dim3(16, 8), ATT_SMEM_BYTES>>>(out);
}

// round 11
// speedup vs baseline: 4.4162x; 3.2101x over previous
#include <cuda_runtime.h>
#include <cuda_fp16.h>
#include <mma.h>
#include <cstdint>

using namespace nvcuda;

#define NB 2
#define NS 2048
#define ND 1024
#define NH 16
#define NDH 64
#define XN (NB * NS * ND)      // 4194304
#define WN (ND * ND)           // 1048576 = 2^20

// half inputs for the projection GEMMs (Wq pre-scaled by 1/sqrt(DH)),
// and half projected Q/K/V in [b,h,s,dh] for the attention kernel.
__device__ __half g_xh[XN];
__device__ __half g_Wh[3 * WN];
__device__ __half g_Qh[NB * NH * NS * NDH];
__device__ __half g_Kh[NB * NH * NS * NDH];
__device__ __half g_Vh[NB * NH * NS * NDH];

__device__ __forceinline__ void cpa16(uint32_t dst, const void* src) {
    asm volatile("cp.async.cg.shared.global [%0], [%1], 16;\n" :: "r"(dst), "l"(src));
}
__device__ __forceinline__ uint32_t smem_u32(const void* p) {
    uint32_t a;
    asm("{ .reg .u64 t; cvta.to.shared.u64 t, %1; cvt.u32.u64 %0, t; }"
        : "=r"(a) : "l"(p));
    return a;
}

// ===========================================================================
// cvt: fp32 -> fp16 for x and the three weight matrices (Wq gets 0.125).
// (XN + 3*WN)/4 float4s = 1835008 = 7168 blocks * 256 threads.
// ===========================================================================
__global__ __launch_bounds__(256) void cvt_kernel(const float* __restrict__ x,
                                                  const float* __restrict__ Wq,
                                                  const float* __restrict__ Wk,
                                                  const float* __restrict__ Wv)
{
    size_t e = ((size_t)blockIdx.x * 256 + threadIdx.x) * 4;
    const float* src;
    __half* dst;
    float sc = 1.0f;
    if (e < XN) {
        src = x + e;
        dst = g_xh + e;
    } else {
        size_t r = e - XN;
        int w = (int)(r >> 20);
        size_t off = r & (WN - 1);
        src = (w == 0 ? Wq : (w == 1 ? Wk : Wv)) + off;
        dst = g_Wh + (size_t)w * WN + off;
        if (w == 0) sc = 0.125f;   // 1/sqrt(64) folded into Wq
    }
    float4 v = *(const float4*)src;
    __half2* d2 = reinterpret_cast<__half2*>(dst);
    d2[0] = __floats2half2_rn(v.x * sc, v.y * sc);
    d2[1] = __floats2half2_rn(v.z * sc, v.w * sc);
}

// ===========================================================================
// Projection GEMM: fp16 wmma m16n16k16, 128x128 tile, K-tile 32,
// 3-stage cp.async pipeline. dst(half)[b,h,s,dh] = xh[m][k] * Wh[k][n].
// 256 threads = 8 warps (2m x 4n), warp tile 64x32 = 4x2 fragments.
// ===========================================================================
#define PKT 32
#define AS_S 40                  // halves: 32 + 8 pad (80B rows, 16B-mult)
#define BS_S 136                 // halves: 128 + 8 pad (272B rows)
#define STAGE_H (128 * AS_S + PKT * BS_S)      // 5120 + 4352 = 9472 halves
#define PROJ_SMEM (3 * STAGE_H * 2)            // 56832 B

__global__ __launch_bounds__(256, 2) void proj_fp16()
{
    extern __shared__ char smraw[];
    __half* sh = reinterpret_cast<__half*>(smraw);

    const int which = blockIdx.z;
    const __half* __restrict__ W = g_Wh + (size_t)which * WN;
    __half* dst = (which == 0) ? g_Qh : (which == 1) ? g_Kh : g_Vh;

    const int m0 = blockIdx.y * 128;
    const int n0 = blockIdx.x * 128;
    const int tid = threadIdx.x;
    const int warp = tid >> 5;
    const int lane = tid & 31;
    const int wm = warp >> 2;        // 0..1 -> m offset wm*64
    const int wn = warp & 3;         // 0..3 -> n offset wn*32

    const __half* __restrict__ xbase = g_xh + (size_t)m0 * ND;

    wmma::fragment<wmma::accumulator, 16, 16, 16, float> acc[4][2];
    #pragma unroll
    for (int i = 0; i < 4; i++)
        #pragma unroll
        for (int j = 0; j < 2; j++)
            wmma::fill_fragment(acc[i][j], 0.0f);

    auto issue = [&](int ki, int st) {
        __half* As = sh + st * STAGE_H;
        __half* Bs = As + 128 * AS_S;
        const int kk0 = ki * PKT;
        #pragma unroll
        for (int i = 0; i < 2; i++) {            // A: 128x32 halves
            int f = tid + i * 256;
            int row = f >> 2, c8 = (f & 3) * 8;
            cpa16(smem_u32(&As[row * AS_S + c8]),
                  xbase + (size_t)row * ND + kk0 + c8);
        }
        #pragma unroll
        for (int i = 0; i < 2; i++) {            // B: 32x128 halves
            int f = tid + i * 256;
            int k = f >> 4, n8 = (f & 15) * 8;
            cpa16(smem_u32(&Bs[k * BS_S + n8]),
                  W + (size_t)(kk0 + k) * ND + n0 + n8);
        }
        asm volatile("cp.async.commit_group;\n" ::: "memory");
    };

    issue(0, 0);
    issue(1, 1);

    const int NIT = ND / PKT;   // 32
    for (int it = 0; it < NIT; it++) {
        if (it < NIT - 2) asm volatile("cp.async.wait_group 1;\n" ::: "memory");
        else              asm volatile("cp.async.wait_group 0;\n" ::: "memory");
        __syncthreads();
        if (it + 2 < NIT) issue(it + 2, (it + 2) % 3);

        const __half* As = sh + (it % 3) * STAGE_H;
        const __half* Bs = As + 128 * AS_S;

        #pragma unroll
        for (int ks = 0; ks < 2; ks++) {
            wmma::fragment<wmma::matrix_a, 16, 16, 16, __half, wmma::row_major> af[4];
            wmma::fragment<wmma::matrix_b, 16, 16, 16, __half, wmma::row_major> bf[2];
            #pragma unroll
            for (int i = 0; i < 4; i++)
                wmma::load_matrix_sync(af[i], &As[(wm * 64 + i * 16) * AS_S + ks * 16], AS_S);
            #pragma unroll
            for (int j = 0; j < 2; j++)
                wmma::load_matrix_sync(bf[j], &Bs[(ks * 16) * BS_S + wn * 32 + j * 16], BS_S);
            #pragma unroll
            for (int i = 0; i < 4; i++)
                #pragma unroll
                for (int j = 0; j < 2; j++)
                    wmma::mma_sync(acc[i][j], af[i], bf[j], acc[i][j]);
        }
    }

    // Epilogue: fp32 frags -> half, scatter into [b,h,s,dh].
    __syncthreads();                                 // all compute done; reuse smem
    float* stg = reinterpret_cast<float*>(smraw) + warp * 256;  // 16x16 staging

    #pragma unroll
    for (int i = 0; i < 4; i++) {
        #pragma unroll
        for (int j = 0; j < 2; j++) {
            wmma::store_matrix_sync(stg, acc[i][j], 16, wmma::mem_row_major);
            __syncwarp();
            const int row = lane >> 1;
            const int col = (lane & 1) * 8;
            float4 f0 = *(float4*)(stg + row * 16 + col);
            float4 f1 = *(float4*)(stg + row * 16 + col + 4);
            __half2 q0 = __floats2half2_rn(f0.x, f0.y);
            __half2 q1 = __floats2half2_rn(f0.z, f0.w);
            __half2 q2 = __floats2half2_rn(f1.x, f1.y);
            __half2 q3 = __floats2half2_rn(f1.z, f1.w);
            uint4 u;
            u.x = *reinterpret_cast<unsigned*>(&q0);
            u.y = *reinterpret_cast<unsigned*>(&q1);
            u.z = *reinterpret_cast<unsigned*>(&q2);
            u.w = *reinterpret_cast<unsigned*>(&q3);

            const int gm = m0 + wm * 64 + i * 16 + row;
            const int b = gm >> 11;
            const int s = gm & (NS - 1);
            const int gn = n0 + wn * 32 + j * 16;
            const int h = gn >> 6;
            const int cc = (gn & 63) + col;
            *(uint4*)(dst + ((size_t)(b * NH + h) * NS + s) * NDH + cc) = u;
            __syncwarp();
        }
    }
}

// ===========================================================================
// Flash attention (causal), fp16 wmma matmuls + fp32 softmax/accumulators.
// One block = one (b,h) x one 64-query tile. 128 threads = 4 warps;
// warp w owns q-rows [16w, 16w+16). O accumulators live in smem fp32 and are
// rescaled by alpha in the scalar softmax pass (online softmax).
// ===========================================================================
#define HS 72                        // half row stride (64 + 8)
#define FS 72                        // float row stride
#define OFF_Q  0                     // Qh 64x72 half  9216 B
#define OFF_K  9216                  // Kh             9216
#define OFF_V  18432                 // Vh             9216
#define OFF_P  27648                 // Ph             9216
#define OFF_S  36864                 // Sf 64x72 fp32  18432
#define OFF_O  55296                 // Of 64x72 fp32  18432
#define ATT_SMEM 73728

__global__ __launch_bounds__(128) void attn_fp16(float* __restrict__ out)
{
    extern __shared__ char smraw[];
    __half* Qh = reinterpret_cast<__half*>(smraw + OFF_Q);
    __half* Kh = reinterpret_cast<__half*>(smraw + OFF_K);
    __half* Vh = reinterpret_cast<__half*>(smraw + OFF_V);
    __half* Ph = reinterpret_cast<__half*>(smraw + OFF_P);
    float*  Sf = reinterpret_cast<float*>(smraw + OFF_S);
    float*  Of = reinterpret_cast<float*>(smraw + OFF_O);

    const int tid = threadIdx.x;
    const int warp = tid >> 5;
    const int bh = blockIdx.y;
    const int qt = gridDim.x - 1 - blockIdx.x;   // big q-tiles first
    const int q0 = qt * 64;

    const __half* __restrict__ Qg = g_Qh + (size_t)bh * NS * NDH;
    const __half* __restrict__ Kg = g_Kh + (size_t)bh * NS * NDH;
    const __half* __restrict__ Vg = g_Vh + (size_t)bh * NS * NDH;

    // Zero O accumulator; load Q tile (64x64 halves).
    #pragma unroll
    for (int t = 0; t < 36; t++)
        Of[tid + t * 128] = 0.0f;
    #pragma unroll
    for (int i = 0; i < 4; i++) {
        int idx = tid + i * 128;              // 512 16B-chunks
        int r = idx >> 3, d8 = (idx & 7) * 8;
        *(uint4*)(Qh + r * HS + d8) = *(const uint4*)(Qg + (size_t)(q0 + r) * NDH + d8);
    }

    // Per-thread softmax state: thread owns row r = tid>>1, cols (tid&1)*32..+31.
    const int r = tid >> 1;
    const int cb = (tid & 1) * 32;
    float m = -1e30f, l = 0.0f;

    for (int kt = 0; kt <= qt; kt++) {
        const int k0 = kt * 64;

        __syncthreads();   // prior PV (reads Vh/Ph/Of) done before overwriting K/V
        #pragma unroll
        for (int i = 0; i < 4; i++) {
            int idx = tid + i * 128;
            int c = idx >> 3, d8 = (idx & 7) * 8;
            *(uint4*)(Kh + c * HS + d8) = *(const uint4*)(Kg + (size_t)(k0 + c) * NDH + d8);
            *(uint4*)(Vh + c * HS + d8) = *(const uint4*)(Vg + (size_t)(k0 + c) * NDH + d8);
        }
        __syncthreads();

        // S = Q K^T  (warp: 16 rows x 64 cols)
        {
            wmma::fragment<wmma::matrix_a, 16, 16, 16, __half, wmma::row_major> af[4];
            #pragma unroll
            for (int kf = 0; kf < 4; kf++)
                wmma::load_matrix_sync(af[kf], Qh + (warp * 16) * HS + kf * 16, HS);
            #pragma unroll
            for (int nf = 0; nf < 4; nf++) {
                wmma::fragment<wmma::accumulator, 16, 16, 16, float> sacc;
                wmma::fill_fragment(sacc, 0.0f);
                #pragma unroll
                for (int kf = 0; kf < 4; kf++) {
                    wmma::fragment<wmma::matrix_b, 16, 16, 16, __half, wmma::col_major> bf;
                    wmma::load_matrix_sync(bf, Kh + (nf * 16) * HS + kf * 16, HS);
                    wmma::mma_sync(sacc, af[kf], bf, sacc);
                }
                wmma::store_matrix_sync(Sf + (warp * 16) * FS + nf * 16, sacc, FS,
                                        wmma::mem_row_major);
            }
        }
        __syncthreads();

        // Scalar fp32 online softmax on Sf rows; write P (half); rescale O.
        {
            float s[32];
            #pragma unroll
            for (int c = 0; c < 32; c += 4)
                *(float4*)&s[c] = *(float4*)&Sf[r * FS + cb + c];

            if (kt == qt) {
                #pragma unroll
                for (int c = 0; c < 32; c++)
                    if (cb + c > r) s[c] = -1e30f;
            }

            float mx = -1e30f;
            #pragma unroll
            for (int c = 0; c < 32; c++) mx = fmaxf(mx, s[c]);
            mx = fmaxf(mx, __shfl_xor_sync(0xffffffffu, mx, 1));

            float mnew = fmaxf(m, mx);
            float alpha = __expf(m - mnew);

            float ps = 0.0f;
            #pragma unroll
            for (int c = 0; c < 32; c++) {
                s[c] = __expf(s[c] - mnew);
                ps += s[c];
            }
            ps += __shfl_xor_sync(0xffffffffu, ps, 1);
            l = l * alpha + ps;
            m = mnew;

            __half2* pr = reinterpret_cast<__half2*>(Ph + r * HS + cb);
            #pragma unroll
            for (int c = 0; c < 16; c++)
                pr[c] = __floats2half2_rn(s[2 * c], s[2 * c + 1]);

            #pragma unroll
            for (int c = 0; c < 32; c += 4) {
                float4 o = *(float4*)&Of[r * FS + cb + c];
                o.x *= alpha; o.y *= alpha; o.z *= alpha; o.w *= alpha;
                *(float4*)&Of[r * FS + cb + c] = o;
            }
        }
        __syncthreads();

        // O += P V  (warp: 16 rows x 64 dh-cols, accum staged in smem fp32)
        {
            wmma::fragment<wmma::matrix_a, 16, 16, 16, __half, wmma::row_major> pf[4];
            #pragma unroll
            for (int kf = 0; kf < 4; kf++)
                wmma::load_matrix_sync(pf[kf], Ph + (warp * 16) * HS + kf * 16, HS);
            #pragma unroll
            for (int nf = 0; nf < 4; nf++) {
                wmma::fragment<wmma::accumulator, 16, 16, 16, float> oacc;
                wmma::load_matrix_sync(oacc, Of + (warp * 16) * FS + nf * 16, FS,
                                       wmma::mem_row_major);
                #pragma unroll
                for (int kf = 0; kf < 4; kf++) {
                    wmma::fragment<wmma::matrix_b, 16, 16, 16, __half, wmma::row_major> vf;
                    wmma::load_matrix_sync(vf, Vh + (kf * 16) * HS + nf * 16, HS);
                    wmma::mma_sync(oacc, pf[kf], vf, oacc);
                }
                wmma::store_matrix_sync(Of + (warp * 16) * FS + nf * 16, oacc, FS,
                                        wmma::mem_row_major);
            }
        }
    }
    __syncthreads();

    // Normalize and write out[b, q, h*64 + dh] (fp32).
    const int b = bh / NH;
    const int h = bh % NH;
    const float inv = 1.0f / l;
    float* op = out + ((size_t)(b * NS + q0 + r) * ND) + h * NDH + cb;
    #pragma unroll
    for (int c = 0; c < 32; c += 4) {
        float4 o = *(float4*)&Of[r * FS + cb + c];
        o.x *= inv; o.y *= inv; o.z *= inv; o.w *= inv;
        *(float4*)(op + c) = o;
    }
}

// ---------------------------------------------------------------------------
extern "C" void kernel_launch(void* const* d_in, const int* in_sizes, int n_in,
                              void* d_out, int out_size)
{
    const float* x  = (const float*)d_in[0];
    const float* Wq = (const float*)d_in[1];
    const float* Wk = (const float*)d_in[2];
    const float* Wv = (const float*)d_in[3];
    float* out = (float*)d_out;

    // 1. fp16 conversion (Wq scaled by 1/sqrt(DH))
    cvt_kernel<<<(XN + 3 * WN) / 4 / 256, 256>>>(x, Wq, Wk, Wv);

    // 2. Q/K/V projections (fp16 wmma, pipelined)
    cudaFuncSetAttribute(proj_fp16, cudaFuncAttributeMaxDynamicSharedMemorySize,
                         PROJ_SMEM);
    dim3 gproj(ND / 128, (NB * NS) / 128, 3);
    proj_fp16<<<gproj, 256, PROJ_SMEM>>>();

    // 3. causal flash attention (fp16 wmma + fp32 softmax)
    cudaFuncSetAttribute(attn_fp16, cudaFuncAttributeMaxDynamicSharedMemorySize,
                         ATT_SMEM);
    dim3 gattn(NS / 64, NB * NH);
    attn_fp16<<<gattn, 128, ATT_SMEM>>>(out);
}